// round 8
// baseline (speedup 1.0000x reference)
#include <cuda_runtime.h>
#include <cuda_fp16.h>
#include <cstdint>

#define S_LEN 2048
#define HD    512        // H_NUM * D_DIM
#define H_NUM 8
#define QT    128        // queries per block
#define STR   144        // smem row stride in BYTES (72 fp16): conflict-free ldmatrix

#define OFF_QHI 0
#define OFF_QLO (OFF_QHI + 128 * STR)
#define OFF_KHI (OFF_QLO + 128 * STR)
#define OFF_KLO (OFF_KHI + 256 * STR)
#define OFF_VHI (OFF_KLO + 256 * STR)
#define OFF_VLO (OFF_VHI + 256 * STR)
#define SMEM_BYTES (OFF_VLO + 256 * STR)   // 184320

__device__ __forceinline__ uint32_t smem_u32(const void* p) {
    uint32_t a;
    asm("{ .reg .u64 t; cvta.to.shared.u64 t, %1; cvt.u32.u64 %0, t; }" : "=r"(a) : "l"(p));
    return a;
}
__device__ __forceinline__ void ldsm4(uint32_t* r, uint32_t a) {
    asm volatile("ldmatrix.sync.aligned.m8n8.x4.shared.b16 {%0,%1,%2,%3}, [%4];"
                 : "=r"(r[0]), "=r"(r[1]), "=r"(r[2]), "=r"(r[3]) : "r"(a));
}
__device__ __forceinline__ void ldsm4t(uint32_t* r, uint32_t a) {
    asm volatile("ldmatrix.sync.aligned.m8n8.x4.trans.shared.b16 {%0,%1,%2,%3}, [%4];"
                 : "=r"(r[0]), "=r"(r[1]), "=r"(r[2]), "=r"(r[3]) : "r"(a));
}
__device__ __forceinline__ void mma_f16(float* c, const uint32_t* a, uint32_t b0, uint32_t b1) {
    asm volatile("mma.sync.aligned.m16n8k16.row.col.f32.f16.f16.f32 "
                 "{%0,%1,%2,%3},{%4,%5,%6,%7},{%8,%9},{%0,%1,%2,%3};"
                 : "+f"(c[0]), "+f"(c[1]), "+f"(c[2]), "+f"(c[3])
                 : "r"(a[0]), "r"(a[1]), "r"(a[2]), "r"(a[3]), "r"(b0), "r"(b1));
}
__device__ __forceinline__ uint32_t pack_h2(float a, float b) {
    __half2 t = __floats2half2_rn(a, b);
    return *reinterpret_cast<uint32_t*>(&t);
}
__device__ __forceinline__ void split2h(float a, float b, uint32_t& hi, uint32_t& lo) {
    float ah = __half2float(__float2half_rn(a));
    float bh = __half2float(__float2half_rn(b));
    hi = pack_h2(a, b);
    lo = pack_h2(a - ah, b - bh);
}
__device__ __forceinline__ float round_h(float x) {
    return __half2float(__float2half_rn(x));
}

__global__ __launch_bounds__(512, 1)
void mca_swa_f16_kernel(const float* __restrict__ Q,
                        const float* __restrict__ K,
                        const float* __restrict__ V,
                        float* __restrict__ O)
{
    extern __shared__ unsigned char sm[];
    const uint32_t sbase = smem_u32(sm);
    const int tid = threadIdx.x;
    const int q0  = blockIdx.x * QT;
    const int h   = blockIdx.y;

    // ---------- Phase 1: Q (all) + K/V rows [0,192) ----------
    #pragma unroll
    for (int i = 0; i < 4; i++) {
        int idx = tid + 512 * i;          // 0..2047 float4
        int row = idx >> 4;
        int d0  = (idx & 15) * 4;
        float4 t = *reinterpret_cast<const float4*>(Q + ((size_t)(q0 + row) * H_NUM + h) * 64 + d0);
        t.x *= 0.125f; t.y *= 0.125f; t.z *= 0.125f; t.w *= 0.125f;
        uint32_t h01, l01, h23, l23;
        split2h(t.x, t.y, h01, l01);
        split2h(t.z, t.w, h23, l23);
        int off = row * STR + d0 * 2;
        *reinterpret_cast<uint2*>(sm + OFF_QHI + off) = make_uint2(h01, h23);
        *reinterpret_cast<uint2*>(sm + OFF_QLO + off) = make_uint2(l01, l23);
    }
    #pragma unroll
    for (int i = 0; i < 6; i++) {
        int idx = tid + 512 * i;          // 0..3071 float4 -> rows [0,192)
        int row = idx >> 4;
        int d0  = (idx & 15) * 4;
        int key = q0 - 64 + row;
        float4 tk = make_float4(0.f, 0.f, 0.f, 0.f);
        float4 tv = make_float4(0.f, 0.f, 0.f, 0.f);
        if ((unsigned)key < (unsigned)S_LEN) {
            size_t base = ((size_t)key * H_NUM + h) * 64 + d0;
            tk = *reinterpret_cast<const float4*>(K + base);
            tv = *reinterpret_cast<const float4*>(V + base);
        }
        int off = row * STR + d0 * 2;
        uint32_t h01, l01, h23, l23;
        split2h(tk.x, tk.y, h01, l01);
        split2h(tk.z, tk.w, h23, l23);
        *reinterpret_cast<uint2*>(sm + OFF_KHI + off) = make_uint2(h01, h23);
        *reinterpret_cast<uint2*>(sm + OFF_KLO + off) = make_uint2(l01, l23);
        split2h(tv.x, tv.y, h01, l01);
        split2h(tv.z, tv.w, h23, l23);
        *reinterpret_cast<uint2*>(sm + OFF_VHI + off) = make_uint2(h01, h23);
        *reinterpret_cast<uint2*>(sm + OFF_VLO + off) = make_uint2(l01, l23);
    }
    // ---------- pre-issue global loads for rows [192,256) ----------
    float4 krg[2], vrg[2];
    #pragma unroll
    for (int j = 0; j < 2; j++) {
        int t   = tid + 512 * j;          // 0..1023 -> rows [192,256)
        int row = 192 + (t >> 4);
        int d0  = (t & 15) * 4;
        int key = q0 - 64 + row;
        krg[j] = make_float4(0.f, 0.f, 0.f, 0.f);
        vrg[j] = make_float4(0.f, 0.f, 0.f, 0.f);
        if ((unsigned)key < (unsigned)S_LEN) {
            size_t base = ((size_t)key * H_NUM + h) * 64 + d0;
            krg[j] = *reinterpret_cast<const float4*>(K + base);
            vrg[j] = *reinterpret_cast<const float4*>(V + base);
        }
    }
    __syncthreads();

    const int l    = tid & 31;
    const int w    = tid >> 5;
    const int half = w >> 3;              // split-K half
    const int p    = w & 7;               // query-pair id
    const int qr0  = p * 16;

    const uint32_t aOff = (uint32_t)((qr0 + (l & 15)) * STR + (8 * (l >> 4)) * 2);               // A (Q)
    const uint32_t bOff = (uint32_t)(((l & 7) + 8 * (l >> 4)) * STR + (8 * ((l >> 3) & 1)) * 2); // B (K)
    const uint32_t vOff = (uint32_t)(((l & 7) + 8 * ((l >> 3) & 1)) * STR + (8 * (l >> 4)) * 2); // B (V, trans)

    // hoist Qhi A-fragments (group-invariant); Qlo reloaded per group
    uint32_t qh[4][4];
    #pragma unroll
    for (int kk = 0; kk < 4; kk++)
        ldsm4(qh[kk], sbase + OFF_QHI + aOff + kk * 32);

    float oacc[32];
    #pragma unroll
    for (int i = 0; i < 32; i++) oacc[i] = 0.f;
    float rs0 = 0.f, rs1 = 0.f;
    const int mrow0 = qr0 + (l >> 2);

    auto do_group = [&](int g) {
        float sacc[8];
        #pragma unroll
        for (int i = 0; i < 8; i++) sacc[i] = 0.f;
        const uint32_t kbase = sbase + (uint32_t)((qr0 + g * 16) * STR);

        // QK: S = Qh*Kh + Qh*Kl + Ql*Kh (fp16, essentially exact)
        #pragma unroll
        for (int kk = 0; kk < 4; kk++) {
            uint32_t ql_[4], kh_[4], kl_[4];
            ldsm4(ql_, sbase + OFF_QLO + aOff + kk * 32);
            uint32_t baddr = kbase + OFF_KHI + bOff + kk * 32;
            ldsm4(kh_, baddr);
            ldsm4(kl_, baddr + (OFF_KLO - OFF_KHI));
            mma_f16(&sacc[0], qh[kk], kh_[0], kh_[1]);
            mma_f16(&sacc[4], qh[kk], kh_[2], kh_[3]);
            mma_f16(&sacc[0], qh[kk], kl_[0], kl_[1]);
            mma_f16(&sacc[4], qh[kk], kl_[2], kl_[3]);
            mma_f16(&sacc[0], ql_, kh_[0], kh_[1]);
            mma_f16(&sacc[4], ql_, kh_[2], kh_[3]);
        }

        // mask + exp; round P to fp16 (rowsum uses the SAME rounded values)
        const int krow0 = q0 - 64 + qr0 + g * 16;
        const bool interior = (g >= 1) && (g <= 7) && (krow0 >= 0) && (krow0 + 16 <= S_LEN);
        if (interior) {
            #pragma unroll
            for (int i = 0; i < 8; i++) sacc[i] = round_h(__expf(sacc[i]));
            rs0 += sacc[0] + sacc[1] + sacc[4] + sacc[5];
            rs1 += sacc[2] + sacc[3] + sacc[6] + sacc[7];
        } else {
            #pragma unroll
            for (int t = 0; t < 2; t++) {
                const int cb = qr0 + g * 16 + t * 8 + 2 * (l & 3);
                #pragma unroll
                for (int e = 0; e < 4; e++) {
                    int m = mrow0 + ((e >> 1) << 3);
                    int c = cb + (e & 1);
                    int key = q0 - 64 + c;
                    bool v = ((unsigned)(c - m) <= 128u) && ((unsigned)key < (unsigned)S_LEN);
                    float pp = v ? round_h(__expf(sacc[t * 4 + e])) : 0.f;
                    sacc[t * 4 + e] = pp;
                    if (e < 2) rs0 += pp; else rs1 += pp;
                }
            }
        }

        // PV: O += P~ * Vhi + P~ * Vlo (2 passes)
        uint32_t pa[4];
        pa[0] = pack_h2(sacc[0], sacc[1]);
        pa[1] = pack_h2(sacc[2], sacc[3]);
        pa[2] = pack_h2(sacc[4], sacc[5]);
        pa[3] = pack_h2(sacc[6], sacc[7]);
        #pragma unroll
        for (int dg = 0; dg < 4; dg++) {
            uint32_t vaddr = kbase + OFF_VHI + vOff + dg * 32;
            uint32_t vh_[4], vl_[4];
            ldsm4t(vh_, vaddr);
            ldsm4t(vl_, vaddr + (OFF_VLO - OFF_VHI));
            mma_f16(&oacc[dg * 8],     pa, vh_[0], vh_[1]);
            mma_f16(&oacc[dg * 8 + 4], pa, vh_[2], vh_[3]);
            mma_f16(&oacc[dg * 8],     pa, vl_[0], vl_[1]);
            mma_f16(&oacc[dg * 8 + 4], pa, vl_[2], vl_[3]);
        }
    };

    // ---- first two groups (need only rows < 176, already loaded) ----
    if (half == 0) { do_group(0); do_group(2); }
    else           { do_group(1); do_group(3); }

    // ---- Phase 2: convert + store held rows [192,256) ----
    #pragma unroll
    for (int j = 0; j < 2; j++) {
        int t   = tid + 512 * j;
        int row = 192 + (t >> 4);
        int d0  = (t & 15) * 4;
        int off = row * STR + d0 * 2;
        uint32_t h01, l01, h23, l23;
        split2h(krg[j].x, krg[j].y, h01, l01);
        split2h(krg[j].z, krg[j].w, h23, l23);
        *reinterpret_cast<uint2*>(sm + OFF_KHI + off) = make_uint2(h01, h23);
        *reinterpret_cast<uint2*>(sm + OFF_KLO + off) = make_uint2(l01, l23);
        split2h(vrg[j].x, vrg[j].y, h01, l01);
        split2h(vrg[j].z, vrg[j].w, h23, l23);
        *reinterpret_cast<uint2*>(sm + OFF_VHI + off) = make_uint2(h01, h23);
        *reinterpret_cast<uint2*>(sm + OFF_VLO + off) = make_uint2(l01, l23);
    }
    __syncthreads();

    // ---- remaining groups ----
    if (half == 0) { do_group(4); do_group(6); do_group(8); }
    else           { do_group(5); do_group(7); }

    // ---- pairwise split-K reduction through (dead) Q smem region ----
    __syncthreads();
    float* red = reinterpret_cast<float*>(sm) + (size_t)(p * 32 + l) * 34;
    if (half == 1) {
        #pragma unroll
        for (int i = 0; i < 32; i++) red[i] = oacc[i];
        red[32] = rs0;
        red[33] = rs1;
    }
    __syncthreads();
    if (half == 0) {
        #pragma unroll
        for (int i = 0; i < 32; i++) oacc[i] += red[i];
        rs0 += red[32];
        rs1 += red[33];

        rs0 += __shfl_xor_sync(0xffffffffu, rs0, 1);
        rs0 += __shfl_xor_sync(0xffffffffu, rs0, 2);
        rs1 += __shfl_xor_sync(0xffffffffu, rs1, 1);
        rs1 += __shfl_xor_sync(0xffffffffu, rs1, 2);
        const float inv0 = 1.0f / rs0;
        const float inv1 = 1.0f / rs1;

        const int mg = q0 + qr0 + (l >> 2);
        #pragma unroll
        for (int fr = 0; fr < 8; fr++) {
            int col = fr * 8 + 2 * (l & 3);
            float2 r0, r1;
            r0.x = oacc[fr * 4 + 0] * inv0; r0.y = oacc[fr * 4 + 1] * inv0;
            r1.x = oacc[fr * 4 + 2] * inv1; r1.y = oacc[fr * 4 + 3] * inv1;
            *reinterpret_cast<float2*>(O + (size_t)mg * HD + h * 64 + col) = r0;
            *reinterpret_cast<float2*>(O + (size_t)(mg + 8) * HD + h * 64 + col) = r1;
        }
    }
}

extern "C" void kernel_launch(void* const* d_in, const int* in_sizes, int n_in,
                              void* d_out, int out_size)
{
    const float* q = (const float*)d_in[0];
    const float* k = (const float*)d_in[1];
    const float* v = (const float*)d_in[2];
    float* out = (float*)d_out;

    cudaFuncSetAttribute(mca_swa_f16_kernel,
                         cudaFuncAttributeMaxDynamicSharedMemorySize, SMEM_BYTES);

    dim3 grid(S_LEN / QT, H_NUM);
    mca_swa_f16_kernel<<<grid, 512, SMEM_BYTES>>>(q, k, v, out);
}

// round 10
// speedup vs baseline: 1.1633x; 1.1633x over previous
#include <cuda_runtime.h>
#include <cuda_fp16.h>
#include <cstdint>

#define S_LEN 2048
#define HD    512        // H_NUM * D_DIM
#define H_NUM 8
#define QT    128        // queries per block
#define STR   144        // smem row stride in BYTES (72 fp16): conflict-free ldmatrix

#define OFF_QHI 0
#define OFF_QLO (OFF_QHI + 128 * STR)
#define OFF_KHI (OFF_QLO + 128 * STR)
#define OFF_KLO (OFF_KHI + 256 * STR)
#define OFF_VHI (OFF_KLO + 256 * STR)
#define SMEM_BYTES (OFF_VHI + 256 * STR)   // 147456

__device__ __forceinline__ uint32_t smem_u32(const void* p) {
    uint32_t a;
    asm("{ .reg .u64 t; cvta.to.shared.u64 t, %1; cvt.u32.u64 %0, t; }" : "=r"(a) : "l"(p));
    return a;
}
__device__ __forceinline__ void ldsm4(uint32_t* r, uint32_t a) {
    asm volatile("ldmatrix.sync.aligned.m8n8.x4.shared.b16 {%0,%1,%2,%3}, [%4];"
                 : "=r"(r[0]), "=r"(r[1]), "=r"(r[2]), "=r"(r[3]) : "r"(a));
}
__device__ __forceinline__ void ldsm4t(uint32_t* r, uint32_t a) {
    asm volatile("ldmatrix.sync.aligned.m8n8.x4.trans.shared.b16 {%0,%1,%2,%3}, [%4];"
                 : "=r"(r[0]), "=r"(r[1]), "=r"(r[2]), "=r"(r[3]) : "r"(a));
}
__device__ __forceinline__ void mma_f16(float* c, const uint32_t* a, uint32_t b0, uint32_t b1) {
    asm volatile("mma.sync.aligned.m16n8k16.row.col.f32.f16.f16.f32 "
                 "{%0,%1,%2,%3},{%4,%5,%6,%7},{%8,%9},{%0,%1,%2,%3};"
                 : "+f"(c[0]), "+f"(c[1]), "+f"(c[2]), "+f"(c[3])
                 : "r"(a[0]), "r"(a[1]), "r"(a[2]), "r"(a[3]), "r"(b0), "r"(b1));
}
__device__ __forceinline__ uint32_t pack_h2(float a, float b) {
    __half2 t = __floats2half2_rn(a, b);
    return *reinterpret_cast<uint32_t*>(&t);
}
__device__ __forceinline__ void split2h(float a, float b, uint32_t& hi, uint32_t& lo) {
    float ah = __half2float(__float2half_rn(a));
    float bh = __half2float(__float2half_rn(b));
    hi = pack_h2(a, b);
    lo = pack_h2(a - ah, b - bh);
}
__device__ __forceinline__ float round_h(float x) {
    return __half2float(__float2half_rn(x));
}

__global__ __launch_bounds__(512, 1)
void mca_swa_f16_kernel(const float* __restrict__ Q,
                        const float* __restrict__ K,
                        const float* __restrict__ V,
                        float* __restrict__ O)
{
    extern __shared__ unsigned char sm[];
    const uint32_t sbase = smem_u32(sm);
    const int tid = threadIdx.x;
    const int q0  = blockIdx.x * QT;
    const int h   = blockIdx.y;

    // ---------- Phase 1: Q (all) + K/V rows [0,192) ----------
    #pragma unroll
    for (int i = 0; i < 4; i++) {
        int idx = tid + 512 * i;          // 0..2047 float4
        int row = idx >> 4;
        int d0  = (idx & 15) * 4;
        float4 t = *reinterpret_cast<const float4*>(Q + ((size_t)(q0 + row) * H_NUM + h) * 64 + d0);
        t.x *= 0.125f; t.y *= 0.125f; t.z *= 0.125f; t.w *= 0.125f;
        uint32_t h01, l01, h23, l23;
        split2h(t.x, t.y, h01, l01);
        split2h(t.z, t.w, h23, l23);
        int off = row * STR + d0 * 2;
        *reinterpret_cast<uint2*>(sm + OFF_QHI + off) = make_uint2(h01, h23);
        *reinterpret_cast<uint2*>(sm + OFF_QLO + off) = make_uint2(l01, l23);
    }
    #pragma unroll
    for (int i = 0; i < 6; i++) {
        int idx = tid + 512 * i;          // 0..3071 float4 -> rows [0,192)
        int row = idx >> 4;
        int d0  = (idx & 15) * 4;
        int key = q0 - 64 + row;
        float4 tk = make_float4(0.f, 0.f, 0.f, 0.f);
        float4 tv = make_float4(0.f, 0.f, 0.f, 0.f);
        if ((unsigned)key < (unsigned)S_LEN) {
            size_t base = ((size_t)key * H_NUM + h) * 64 + d0;
            tk = *reinterpret_cast<const float4*>(K + base);
            tv = *reinterpret_cast<const float4*>(V + base);
        }
        int off = row * STR + d0 * 2;
        uint32_t h01, l01, h23, l23;
        split2h(tk.x, tk.y, h01, l01);
        split2h(tk.z, tk.w, h23, l23);
        *reinterpret_cast<uint2*>(sm + OFF_KHI + off) = make_uint2(h01, h23);
        *reinterpret_cast<uint2*>(sm + OFF_KLO + off) = make_uint2(l01, l23);
        *reinterpret_cast<uint2*>(sm + OFF_VHI + off) =
            make_uint2(pack_h2(tv.x, tv.y), pack_h2(tv.z, tv.w));
    }
    // ---------- pre-issue global loads for rows [192,256) ----------
    float4 krg[2], vrg[2];
    #pragma unroll
    for (int j = 0; j < 2; j++) {
        int t   = tid + 512 * j;          // 0..1023 -> rows [192,256)
        int row = 192 + (t >> 4);
        int d0  = (t & 15) * 4;
        int key = q0 - 64 + row;
        krg[j] = make_float4(0.f, 0.f, 0.f, 0.f);
        vrg[j] = make_float4(0.f, 0.f, 0.f, 0.f);
        if ((unsigned)key < (unsigned)S_LEN) {
            size_t base = ((size_t)key * H_NUM + h) * 64 + d0;
            krg[j] = *reinterpret_cast<const float4*>(K + base);
            vrg[j] = *reinterpret_cast<const float4*>(V + base);
        }
    }
    __syncthreads();

    const int l    = tid & 31;
    const int w    = tid >> 5;
    const int half = w >> 3;              // split-K half
    const int p    = w & 7;               // query-pair id
    const int qr0  = p * 16;

    const uint32_t aOff = (uint32_t)((qr0 + (l & 15)) * STR + (8 * (l >> 4)) * 2);               // A (Q)
    const uint32_t bOff = (uint32_t)(((l & 7) + 8 * (l >> 4)) * STR + (8 * ((l >> 3) & 1)) * 2); // B (K)
    const uint32_t vOff = (uint32_t)(((l & 7) + 8 * ((l >> 3) & 1)) * STR + (8 * (l >> 4)) * 2); // B (V, trans)

    // hoist Qhi A-fragments (group-invariant); Qlo reloaded per group
    uint32_t qh[4][4];
    #pragma unroll
    for (int kk = 0; kk < 4; kk++)
        ldsm4(qh[kk], sbase + OFF_QHI + aOff + kk * 32);

    float oacc[32];
    #pragma unroll
    for (int i = 0; i < 32; i++) oacc[i] = 0.f;
    float rs0 = 0.f, rs1 = 0.f;
    const int mrow0 = qr0 + (l >> 2);

    auto do_group = [&](int g) {
        float sacc[8];
        #pragma unroll
        for (int i = 0; i < 8; i++) sacc[i] = 0.f;
        const uint32_t kbase = sbase + (uint32_t)((qr0 + g * 16) * STR);

        // QK: S = Qh*Kh + Qh*Kl + Ql*Kh (3-pass fp16, essentially exact)
        #pragma unroll
        for (int kk = 0; kk < 4; kk++) {
            uint32_t ql_[4], kh_[4], kl_[4];
            ldsm4(ql_, sbase + OFF_QLO + aOff + kk * 32);
            uint32_t baddr = kbase + OFF_KHI + bOff + kk * 32;
            ldsm4(kh_, baddr);
            ldsm4(kl_, baddr + (OFF_KLO - OFF_KHI));
            mma_f16(&sacc[0], qh[kk], kh_[0], kh_[1]);
            mma_f16(&sacc[4], qh[kk], kh_[2], kh_[3]);
            mma_f16(&sacc[0], qh[kk], kl_[0], kl_[1]);
            mma_f16(&sacc[4], qh[kk], kl_[2], kl_[3]);
            mma_f16(&sacc[0], ql_, kh_[0], kh_[1]);
            mma_f16(&sacc[4], ql_, kh_[2], kh_[3]);
        }

        // mask + exp; round P to fp16 (rowsum uses the SAME rounded values)
        const int krow0 = q0 - 64 + qr0 + g * 16;
        const bool interior = (g >= 1) && (g <= 7) && (krow0 >= 0) && (krow0 + 16 <= S_LEN);
        if (interior) {
            #pragma unroll
            for (int i = 0; i < 8; i++) sacc[i] = round_h(__expf(sacc[i]));
            rs0 += sacc[0] + sacc[1] + sacc[4] + sacc[5];
            rs1 += sacc[2] + sacc[3] + sacc[6] + sacc[7];
        } else {
            #pragma unroll
            for (int t = 0; t < 2; t++) {
                const int cb = qr0 + g * 16 + t * 8 + 2 * (l & 3);
                #pragma unroll
                for (int e = 0; e < 4; e++) {
                    int m = mrow0 + ((e >> 1) << 3);
                    int c = cb + (e & 1);
                    int key = q0 - 64 + c;
                    bool v = ((unsigned)(c - m) <= 128u) && ((unsigned)key < (unsigned)S_LEN);
                    float pp = v ? round_h(__expf(sacc[t * 4 + e])) : 0.f;
                    sacc[t * 4 + e] = pp;
                    if (e < 2) rs0 += pp; else rs1 += pp;
                }
            }
        }

        // PV: O += P~ * V (single fp16 pass)
        uint32_t pa[4];
        pa[0] = pack_h2(sacc[0], sacc[1]);
        pa[1] = pack_h2(sacc[2], sacc[3]);
        pa[2] = pack_h2(sacc[4], sacc[5]);
        pa[3] = pack_h2(sacc[6], sacc[7]);
        #pragma unroll
        for (int dg = 0; dg < 4; dg++) {
            uint32_t vh_[4];
            ldsm4t(vh_, kbase + OFF_VHI + vOff + dg * 32);
            mma_f16(&oacc[dg * 8],     pa, vh_[0], vh_[1]);
            mma_f16(&oacc[dg * 8 + 4], pa, vh_[2], vh_[3]);
        }
    };

    // ---- first two groups (need only rows < 176, already loaded) ----
    if (half == 0) { do_group(0); do_group(2); }
    else           { do_group(1); do_group(3); }

    // ---- Phase 2: convert + store held rows [192,256) ----
    #pragma unroll
    for (int j = 0; j < 2; j++) {
        int t   = tid + 512 * j;
        int row = 192 + (t >> 4);
        int d0  = (t & 15) * 4;
        int off = row * STR + d0 * 2;
        uint32_t h01, l01, h23, l23;
        split2h(krg[j].x, krg[j].y, h01, l01);
        split2h(krg[j].z, krg[j].w, h23, l23);
        *reinterpret_cast<uint2*>(sm + OFF_KHI + off) = make_uint2(h01, h23);
        *reinterpret_cast<uint2*>(sm + OFF_KLO + off) = make_uint2(l01, l23);
        *reinterpret_cast<uint2*>(sm + OFF_VHI + off) =
            make_uint2(pack_h2(vrg[j].x, vrg[j].y), pack_h2(vrg[j].z, vrg[j].w));
    }
    __syncthreads();

    // ---- remaining groups ----
    if (half == 0) { do_group(4); do_group(6); do_group(8); }
    else           { do_group(5); do_group(7); }

    // ---- pairwise split-K reduction through (dead) Q smem region ----
    __syncthreads();
    float* red = reinterpret_cast<float*>(sm) + (size_t)(p * 32 + l) * 34;
    if (half == 1) {
        #pragma unroll
        for (int i = 0; i < 32; i++) red[i] = oacc[i];
        red[32] = rs0;
        red[33] = rs1;
    }
    __syncthreads();
    if (half == 0) {
        #pragma unroll
        for (int i = 0; i < 32; i++) oacc[i] += red[i];
        rs0 += red[32];
        rs1 += red[33];

        rs0 += __shfl_xor_sync(0xffffffffu, rs0, 1);
        rs0 += __shfl_xor_sync(0xffffffffu, rs0, 2);
        rs1 += __shfl_xor_sync(0xffffffffu, rs1, 1);
        rs1 += __shfl_xor_sync(0xffffffffu, rs1, 2);
        const float inv0 = 1.0f / rs0;
        const float inv1 = 1.0f / rs1;

        const int mg = q0 + qr0 + (l >> 2);
        #pragma unroll
        for (int fr = 0; fr < 8; fr++) {
            int col = fr * 8 + 2 * (l & 3);
            float2 r0, r1;
            r0.x = oacc[fr * 4 + 0] * inv0; r0.y = oacc[fr * 4 + 1] * inv0;
            r1.x = oacc[fr * 4 + 2] * inv1; r1.y = oacc[fr * 4 + 3] * inv1;
            *reinterpret_cast<float2*>(O + (size_t)mg * HD + h * 64 + col) = r0;
            *reinterpret_cast<float2*>(O + (size_t)(mg + 8) * HD + h * 64 + col) = r1;
        }
    }
}

extern "C" void kernel_launch(void* const* d_in, const int* in_sizes, int n_in,
                              void* d_out, int out_size)
{
    const float* q = (const float*)d_in[0];
    const float* k = (const float*)d_in[1];
    const float* v = (const float*)d_in[2];
    float* out = (float*)d_out;

    cudaFuncSetAttribute(mca_swa_f16_kernel,
                         cudaFuncAttributeMaxDynamicSharedMemorySize, SMEM_BYTES);

    dim3 grid(S_LEN / QT, H_NUM);
    mca_swa_f16_kernel<<<grid, 512, SMEM_BYTES>>>(q, k, v, out);
}

// round 11
// speedup vs baseline: 1.1910x; 1.0239x over previous
#include <cuda_runtime.h>
#include <cuda_fp16.h>
#include <cstdint>

#define S_LEN 2048
#define HD    512        // H_NUM * D_DIM
#define H_NUM 8
#define QT    128        // queries per block
#define STR   144        // smem row stride in BYTES (72 fp16): conflict-free ldmatrix

#define OFF_QHI 0
#define OFF_KHI (OFF_QHI + 128 * STR)
#define OFF_KLO (OFF_KHI + 256 * STR)
#define OFF_VHI (OFF_KLO + 256 * STR)
#define SMEM_BYTES (OFF_VHI + 256 * STR)   // 129024

__device__ __forceinline__ uint32_t smem_u32(const void* p) {
    uint32_t a;
    asm("{ .reg .u64 t; cvta.to.shared.u64 t, %1; cvt.u32.u64 %0, t; }" : "=r"(a) : "l"(p));
    return a;
}
__device__ __forceinline__ void ldsm4(uint32_t* r, uint32_t a) {
    asm volatile("ldmatrix.sync.aligned.m8n8.x4.shared.b16 {%0,%1,%2,%3}, [%4];"
                 : "=r"(r[0]), "=r"(r[1]), "=r"(r[2]), "=r"(r[3]) : "r"(a));
}
__device__ __forceinline__ void ldsm4t(uint32_t* r, uint32_t a) {
    asm volatile("ldmatrix.sync.aligned.m8n8.x4.trans.shared.b16 {%0,%1,%2,%3}, [%4];"
                 : "=r"(r[0]), "=r"(r[1]), "=r"(r[2]), "=r"(r[3]) : "r"(a));
}
__device__ __forceinline__ void mma_f16(float* c, const uint32_t* a, uint32_t b0, uint32_t b1) {
    asm volatile("mma.sync.aligned.m16n8k16.row.col.f32.f16.f16.f32 "
                 "{%0,%1,%2,%3},{%4,%5,%6,%7},{%8,%9},{%0,%1,%2,%3};"
                 : "+f"(c[0]), "+f"(c[1]), "+f"(c[2]), "+f"(c[3])
                 : "r"(a[0]), "r"(a[1]), "r"(a[2]), "r"(a[3]), "r"(b0), "r"(b1));
}
__device__ __forceinline__ uint32_t pack_h2(float a, float b) {
    __half2 t = __floats2half2_rn(a, b);
    return *reinterpret_cast<uint32_t*>(&t);
}
__device__ __forceinline__ void split2h(float a, float b, uint32_t& hi, uint32_t& lo) {
    float ah = __half2float(__float2half_rn(a));
    float bh = __half2float(__float2half_rn(b));
    hi = pack_h2(a, b);
    lo = pack_h2(a - ah, b - bh);
}
__device__ __forceinline__ float round_h(float x) {
    return __half2float(__float2half_rn(x));
}

__global__ __launch_bounds__(512, 1)
void mca_swa_f16_kernel(const float* __restrict__ Q,
                        const float* __restrict__ K,
                        const float* __restrict__ V,
                        float* __restrict__ O)
{
    extern __shared__ unsigned char sm[];
    const uint32_t sbase = smem_u32(sm);
    const int tid = threadIdx.x;
    const int q0  = blockIdx.x * QT;
    const int h   = blockIdx.y;

    // ---------- Phase 1: Q (all) + K/V rows [0,192) ----------
    #pragma unroll
    for (int i = 0; i < 4; i++) {
        int idx = tid + 512 * i;          // 0..2047 float4
        int row = idx >> 4;
        int d0  = (idx & 15) * 4;
        float4 t = *reinterpret_cast<const float4*>(Q + ((size_t)(q0 + row) * H_NUM + h) * 64 + d0);
        t.x *= 0.125f; t.y *= 0.125f; t.z *= 0.125f; t.w *= 0.125f;
        int off = row * STR + d0 * 2;
        *reinterpret_cast<uint2*>(sm + OFF_QHI + off) =
            make_uint2(pack_h2(t.x, t.y), pack_h2(t.z, t.w));
    }
    #pragma unroll
    for (int i = 0; i < 6; i++) {
        int idx = tid + 512 * i;          // 0..3071 float4 -> rows [0,192)
        int row = idx >> 4;
        int d0  = (idx & 15) * 4;
        int key = q0 - 64 + row;
        float4 tk = make_float4(0.f, 0.f, 0.f, 0.f);
        float4 tv = make_float4(0.f, 0.f, 0.f, 0.f);
        if ((unsigned)key < (unsigned)S_LEN) {
            size_t base = ((size_t)key * H_NUM + h) * 64 + d0;
            tk = *reinterpret_cast<const float4*>(K + base);
            tv = *reinterpret_cast<const float4*>(V + base);
        }
        int off = row * STR + d0 * 2;
        uint32_t h01, l01, h23, l23;
        split2h(tk.x, tk.y, h01, l01);
        split2h(tk.z, tk.w, h23, l23);
        *reinterpret_cast<uint2*>(sm + OFF_KHI + off) = make_uint2(h01, h23);
        *reinterpret_cast<uint2*>(sm + OFF_KLO + off) = make_uint2(l01, l23);
        *reinterpret_cast<uint2*>(sm + OFF_VHI + off) =
            make_uint2(pack_h2(tv.x, tv.y), pack_h2(tv.z, tv.w));
    }
    // ---------- pre-issue global loads for rows [192,256) ----------
    float4 krg[2], vrg[2];
    #pragma unroll
    for (int j = 0; j < 2; j++) {
        int t   = tid + 512 * j;          // 0..1023 -> rows [192,256)
        int row = 192 + (t >> 4);
        int d0  = (t & 15) * 4;
        int key = q0 - 64 + row;
        krg[j] = make_float4(0.f, 0.f, 0.f, 0.f);
        vrg[j] = make_float4(0.f, 0.f, 0.f, 0.f);
        if ((unsigned)key < (unsigned)S_LEN) {
            size_t base = ((size_t)key * H_NUM + h) * 64 + d0;
            krg[j] = *reinterpret_cast<const float4*>(K + base);
            vrg[j] = *reinterpret_cast<const float4*>(V + base);
        }
    }
    __syncthreads();

    const int l    = tid & 31;
    const int w    = tid >> 5;
    const int half = w >> 3;              // split-K half
    const int p    = w & 7;               // query-pair id
    const int qr0  = p * 16;

    const uint32_t aOff = (uint32_t)((qr0 + (l & 15)) * STR + (8 * (l >> 4)) * 2);               // A (Q)
    const uint32_t bOff = (uint32_t)(((l & 7) + 8 * (l >> 4)) * STR + (8 * ((l >> 3) & 1)) * 2); // B (K)
    const uint32_t vOff = (uint32_t)(((l & 7) + 8 * ((l >> 3) & 1)) * STR + (8 * (l >> 4)) * 2); // B (V, trans)

    // hoist Qhi A-fragments (group-invariant; Qlo pass dropped entirely)
    uint32_t qh[4][4];
    #pragma unroll
    for (int kk = 0; kk < 4; kk++)
        ldsm4(qh[kk], sbase + OFF_QHI + aOff + kk * 32);

    float oacc[32];
    #pragma unroll
    for (int i = 0; i < 32; i++) oacc[i] = 0.f;
    float rs0 = 0.f, rs1 = 0.f;
    const int mrow0 = qr0 + (l >> 2);

    auto do_group = [&](int g) {
        float sacc[8];
        #pragma unroll
        for (int i = 0; i < 8; i++) sacc[i] = 0.f;
        const uint32_t kbase = sbase + (uint32_t)((qr0 + g * 16) * STR);

        // QK: S = Qh*Kh + Qh*Kl (2-pass fp16)
        #pragma unroll
        for (int kk = 0; kk < 4; kk++) {
            uint32_t kh_[4], kl_[4];
            uint32_t baddr = kbase + OFF_KHI + bOff + kk * 32;
            ldsm4(kh_, baddr);
            ldsm4(kl_, baddr + (OFF_KLO - OFF_KHI));
            mma_f16(&sacc[0], qh[kk], kh_[0], kh_[1]);
            mma_f16(&sacc[4], qh[kk], kh_[2], kh_[3]);
            mma_f16(&sacc[0], qh[kk], kl_[0], kl_[1]);
            mma_f16(&sacc[4], qh[kk], kl_[2], kl_[3]);
        }

        // mask + exp; round P to fp16 (rowsum uses the SAME rounded values)
        const int krow0 = q0 - 64 + qr0 + g * 16;
        const bool interior = (g >= 1) && (g <= 7) && (krow0 >= 0) && (krow0 + 16 <= S_LEN);
        if (interior) {
            #pragma unroll
            for (int i = 0; i < 8; i++) sacc[i] = round_h(__expf(sacc[i]));
            rs0 += sacc[0] + sacc[1] + sacc[4] + sacc[5];
            rs1 += sacc[2] + sacc[3] + sacc[6] + sacc[7];
        } else {
            #pragma unroll
            for (int t = 0; t < 2; t++) {
                const int cb = qr0 + g * 16 + t * 8 + 2 * (l & 3);
                #pragma unroll
                for (int e = 0; e < 4; e++) {
                    int m = mrow0 + ((e >> 1) << 3);
                    int c = cb + (e & 1);
                    int key = q0 - 64 + c;
                    bool v = ((unsigned)(c - m) <= 128u) && ((unsigned)key < (unsigned)S_LEN);
                    float pp = v ? round_h(__expf(sacc[t * 4 + e])) : 0.f;
                    sacc[t * 4 + e] = pp;
                    if (e < 2) rs0 += pp; else rs1 += pp;
                }
            }
        }

        // PV: O += P~ * V (single fp16 pass)
        uint32_t pa[4];
        pa[0] = pack_h2(sacc[0], sacc[1]);
        pa[1] = pack_h2(sacc[2], sacc[3]);
        pa[2] = pack_h2(sacc[4], sacc[5]);
        pa[3] = pack_h2(sacc[6], sacc[7]);
        #pragma unroll
        for (int dg = 0; dg < 4; dg++) {
            uint32_t vh_[4];
            ldsm4t(vh_, kbase + OFF_VHI + vOff + dg * 32);
            mma_f16(&oacc[dg * 8],     pa, vh_[0], vh_[1]);
            mma_f16(&oacc[dg * 8 + 4], pa, vh_[2], vh_[3]);
        }
    };

    // ---- first two groups (need only rows < 176, already loaded) ----
    if (half == 0) { do_group(0); do_group(2); }
    else           { do_group(1); do_group(3); }

    // ---- Phase 2: convert + store held rows [192,256) ----
    #pragma unroll
    for (int j = 0; j < 2; j++) {
        int t   = tid + 512 * j;
        int row = 192 + (t >> 4);
        int d0  = (t & 15) * 4;
        int off = row * STR + d0 * 2;
        uint32_t h01, l01, h23, l23;
        split2h(krg[j].x, krg[j].y, h01, l01);
        split2h(krg[j].z, krg[j].w, h23, l23);
        *reinterpret_cast<uint2*>(sm + OFF_KHI + off) = make_uint2(h01, h23);
        *reinterpret_cast<uint2*>(sm + OFF_KLO + off) = make_uint2(l01, l23);
        *reinterpret_cast<uint2*>(sm + OFF_VHI + off) =
            make_uint2(pack_h2(vrg[j].x, vrg[j].y), pack_h2(vrg[j].z, vrg[j].w));
    }
    __syncthreads();

    // ---- remaining groups ----
    if (half == 0) { do_group(4); do_group(6); do_group(8); }
    else           { do_group(5); do_group(7); }

    // ---- pairwise split-K reduction through (dead) Q smem region ----
    __syncthreads();
    float* red = reinterpret_cast<float*>(sm) + (size_t)(p * 32 + l) * 34;
    if (half == 1) {
        #pragma unroll
        for (int i = 0; i < 32; i++) red[i] = oacc[i];
        red[32] = rs0;
        red[33] = rs1;
    }
    __syncthreads();
    if (half == 0) {
        #pragma unroll
        for (int i = 0; i < 32; i++) oacc[i] += red[i];
        rs0 += red[32];
        rs1 += red[33];

        rs0 += __shfl_xor_sync(0xffffffffu, rs0, 1);
        rs0 += __shfl_xor_sync(0xffffffffu, rs0, 2);
        rs1 += __shfl_xor_sync(0xffffffffu, rs1, 1);
        rs1 += __shfl_xor_sync(0xffffffffu, rs1, 2);
        const float inv0 = 1.0f / rs0;
        const float inv1 = 1.0f / rs1;

        const int mg = q0 + qr0 + (l >> 2);
        #pragma unroll
        for (int fr = 0; fr < 8; fr++) {
            int col = fr * 8 + 2 * (l & 3);
            float2 r0, r1;
            r0.x = oacc[fr * 4 + 0] * inv0; r0.y = oacc[fr * 4 + 1] * inv0;
            r1.x = oacc[fr * 4 + 2] * inv1; r1.y = oacc[fr * 4 + 3] * inv1;
            *reinterpret_cast<float2*>(O + (size_t)mg * HD + h * 64 + col) = r0;
            *reinterpret_cast<float2*>(O + (size_t)(mg + 8) * HD + h * 64 + col) = r1;
        }
    }
}

extern "C" void kernel_launch(void* const* d_in, const int* in_sizes, int n_in,
                              void* d_out, int out_size)
{
    const float* q = (const float*)d_in[0];
    const float* k = (const float*)d_in[1];
    const float* v = (const float*)d_in[2];
    float* out = (float*)d_out;

    cudaFuncSetAttribute(mca_swa_f16_kernel,
                         cudaFuncAttributeMaxDynamicSharedMemorySize, SMEM_BYTES);

    dim3 grid(S_LEN / QT, H_NUM);
    mca_swa_f16_kernel<<<grid, 512, SMEM_BYTES>>>(q, k, v, out);
}